// round 7
// baseline (speedup 1.0000x reference)
#include <cuda_runtime.h>

// ---------------------------------------------------------------------------
// EnhancedSegmentationLoss — fully fused:
//   loss_main : streaming Sobel + focal + dice + segment histogram
//               (count+sum packed into ONE float per (thread,bin): v = Σ(64+p))
//   finalize  : contrastive + compose; self-resets accumulators for replay
// ---------------------------------------------------------------------------

#define NB 16
#define NH 1024
#define NW 1024
#define NW4 (NW / 4)
#define NUM_IDS 32
#define R_ROWS 8            // rows per warp strip
#define BTH 128             // threads per block

#define ACC_FOCAL 0
#define ACC_SUMT  1
#define ACC_SUMPT 2
#define ACC_MAG   3
#define ACC_DIR   4
#define ACC_MCNT  5

__device__ float g_acc[8];
__device__ float g_seg_sum[NB * NUM_IDS];
__device__ float g_seg_cnt[NB * NUM_IDS];

__device__ __forceinline__ float sigf(float x) {
    return __fdividef(1.f, 1.f + __expf(-x));
}

// separable sobel row terms for one row of 4 px (per thread)
__device__ __forceinline__ void row_terms(
    float4 pv, float4 tv, float pe, float te, int lane,
    float* __restrict__ dp, float* __restrict__ sp,
    float* __restrict__ dt, float* __restrict__ st,
    float* __restrict__ pout)
{
    float p0 = sigf(pv.x), p1 = sigf(pv.y), p2 = sigf(pv.z), p3 = sigf(pv.w);
    float pes = sigf(pe);

    float pl = __shfl_up_sync(0xffffffffu, p3, 1);    if (lane == 0)  pl = pes;
    float pr = __shfl_down_sync(0xffffffffu, p0, 1);  if (lane == 31) pr = pes;
    float tl = __shfl_up_sync(0xffffffffu, tv.w, 1);  if (lane == 0)  tl = te;
    float tr = __shfl_down_sync(0xffffffffu, tv.x, 1);if (lane == 31) tr = te;

    dp[0] = 0.125f * (p1 - pl);     dp[1] = 0.125f * (p2 - p0);
    dp[2] = 0.125f * (p3 - p1);     dp[3] = 0.125f * (pr - p2);
    sp[0] = fmaf(0.25f, p0, 0.125f * (pl + p1));
    sp[1] = fmaf(0.25f, p1, 0.125f * (p0 + p2));
    sp[2] = fmaf(0.25f, p2, 0.125f * (p1 + p3));
    sp[3] = fmaf(0.25f, p3, 0.125f * (p2 + pr));
    dt[0] = 0.125f * (tv.y - tl);   dt[1] = 0.125f * (tv.z - tv.x);
    dt[2] = 0.125f * (tv.w - tv.y); dt[3] = 0.125f * (tr - tv.z);
    st[0] = fmaf(0.25f, tv.x, 0.125f * (tl + tv.y));
    st[1] = fmaf(0.25f, tv.y, 0.125f * (tv.x + tv.z));
    st[2] = fmaf(0.25f, tv.z, 0.125f * (tv.y + tv.w));
    st[3] = fmaf(0.25f, tv.w, 0.125f * (tv.z + tr));

    pout[0] = p0; pout[1] = p1; pout[2] = p2; pout[3] = p3;
}

// pointwise losses + packed segment-histogram update for one row of 4 px
__device__ __forceinline__ void pointwise(
    const float* __restrict__ p, float4 tv, int4 id,
    float* __restrict__ hist, int tid,
    float& fl, float& sts, float& spt)
{
    float tt[4] = {tv.x, tv.y, tv.z, tv.w};
    int   ii[4] = {id.x & 31, id.y & 31, id.z & 31, id.w & 31};
    #pragma unroll
    for (int i = 0; i < 4; ++i) {
        float ep  = 1.f - p[i];
        bool  one = (tt[i] == 1.f);
        float pt  = one ? p[i] : ep;
        float om  = one ? ep : p[i];
        float aw  = one ? 0.25f : 0.75f;
        fl  = fmaf(aw * om * om, -__logf(pt), fl);
        sts += tt[i];
        spt = fmaf(tt[i], p[i], spt);
        hist[ii[i] * BTH + tid] += (64.f + p[i]);   // packed count|sum
    }
}

__device__ __forceinline__ void stencil_out(
    const float* dpA, const float* spA, const float* dtA, const float* stA,
    const float* dpB, const float* dtB,
    const float* dpC, const float* spC, const float* dtC, const float* stC,
    float& mag, float& dsum, float& mcnt)
{
    #pragma unroll
    for (int i = 0; i < 4; ++i) {
        float pgx = fmaf(2.f, dpB[i], dpA[i] + dpC[i]);
        float pgy = spC[i] - spA[i];
        float tgx = fmaf(2.f, dtB[i], dtA[i] + dtC[i]);
        float tgy = stC[i] - stA[i];
        float pq = fmaf(pgx, pgx, fmaf(pgy, pgy, 1e-6f));
        float tq = fmaf(tgx, tgx, fmaf(tgy, tgy, 1e-6f));
        float rp = rsqrtf(pq), rt = rsqrtf(tq);
        float pm = pq * rp,    tm = tq * rt;
        float bw = fmaf(5.f, tm, 1.f);
        float dm = (pm - tm) * bw;
        mag = fmaf(dm, dm, mag);
        float sel = (tm > 0.1f) ? 1.f : 0.f;
        float cosv = fmaf(tgx, pgx, tgy * pgy) * (rt * rp);
        dsum = fmaf(sel, 1.f - cosv, dsum);
        mcnt += sel;
    }
}

// ===========================================================================
// Fused kernel: stencil + pointwise + segment histogram
// ===========================================================================
__global__ __launch_bounds__(BTH, 5) void loss_main(
    const float4* __restrict__ pred4,
    const float4* __restrict__ tgt4,
    const int4*   __restrict__ ids4)
{
    __shared__ float hist[NUM_IDS * BTH];   // 16 KB, bank = tid -> conflict-free
    __shared__ float red[4][6];

    const int tid  = threadIdx.x;
    const int lane = tid & 31;
    const int warp = tid >> 5;               // 0..3
    const int b  = blockIdx.z;
    const int x0 = blockIdx.x * 128;
    const int ys = blockIdx.y * (4 * R_ROWS) + warp * R_ROWS;

    // zero histogram (1024 float4 / 128 threads = 8 stores)
    {
        float4 z = make_float4(0.f, 0.f, 0.f, 0.f);
        float4* h4 = (float4*)hist;
        #pragma unroll
        for (int i = 0; i < 8; ++i) h4[tid + i * BTH] = z;
    }
    __syncthreads();

    const int  c4   = (x0 >> 2) + lane;
    const bool edge = (lane == 0) | (lane == 31);
    const int  xe   = (lane == 0) ? max(x0 - 1, 0) : min(x0 + 128, NW - 1);

    const float4* P4 = pred4 + (size_t)b * (NH * NW4) + (size_t)ys * NW4 + c4;
    const float4* T4 = tgt4  + (size_t)b * (NH * NW4) + (size_t)ys * NW4 + c4;
    const int4*   I4 = ids4  + (size_t)b * (NH * NW4) + (size_t)ys * NW4 + c4;
    const float*  Ps = (const float*)pred4 + (size_t)b * NH * NW + (size_t)ys * NW + xe;
    const float*  Ts = (const float*)tgt4  + (size_t)b * NH * NW + (size_t)ys * NW + xe;

    const int top4 = (ys == 0) ? 0 : -NW4;
    const int topS = (ys == 0) ? 0 : -NW;
    const int bot4 = (ys + R_ROWS >= NH) ? (R_ROWS - 1) * NW4 : R_ROWS * NW4;
    const int botS = (ys + R_ROWS >= NH) ? (R_ROWS - 1) * NW  : R_ROWS * NW;

    float fl = 0.f, sts = 0.f, spt = 0.f;
    float mag = 0.f, dsum = 0.f, mcnt = 0.f;

    float dpA[4], spA[4], dtA[4], stA[4];
    float dpB[4], spB[4], dtB[4], stB[4];
    float dpC[4], spC[4], dtC[4], stC[4];
    float pc[4];

    // prologue: halo row (terms only), first output row (terms + pointwise)
    {
        float4 pv = P4[top4], tv = T4[top4];
        float pe = 0.f, te = 0.f;
        if (edge) { pe = Ps[topS]; te = Ts[topS]; }
        row_terms(pv, tv, pe, te, lane, dpA, spA, dtA, stA, pc);
    }
    {
        float4 pv = P4[0], tv = T4[0];
        int4 idv = I4[0];
        float pe = 0.f, te = 0.f;
        if (edge) { pe = Ps[0]; te = Ts[0]; }
        row_terms(pv, tv, pe, te, lane, dpB, spB, dtB, stB, pc);
        pointwise(pc, tv, idv, hist, tid, fl, sts, spt);
    }

    #pragma unroll
    for (int j = 0; j < R_ROWS; ++j) {
        const int o4 = (j == R_ROWS - 1) ? bot4 : (j + 1) * NW4;
        const int oS = (j == R_ROWS - 1) ? botS : (j + 1) * NW;
        float4 pv = P4[o4], tv = T4[o4];
        float pe = 0.f, te = 0.f;
        if (edge) { pe = Ps[oS]; te = Ts[oS]; }
        row_terms(pv, tv, pe, te, lane, dpC, spC, dtC, stC, pc);
        if (j < R_ROWS - 1) {
            int4 idv = I4[(j + 1) * NW4];
            pointwise(pc, tv, idv, hist, tid, fl, sts, spt);
        }

        stencil_out(dpA, spA, dtA, stA, dpB, dtB, dpC, spC, dtC, stC,
                    mag, dsum, mcnt);

        #pragma unroll
        for (int i = 0; i < 4; ++i) {
            dpA[i] = dpB[i]; spA[i] = spB[i]; dtA[i] = dtB[i]; stA[i] = stB[i];
            dpB[i] = dpC[i]; spB[i] = spC[i]; dtB[i] = dtC[i]; stB[i] = stC[i];
        }
    }

    // ---- block reduce 6 scalars -> 1 atomic each ----
    float v[6] = {fl, sts, spt, mag, dsum, mcnt};
    #pragma unroll
    for (int q = 0; q < 6; ++q) {
        #pragma unroll
        for (int off = 16; off; off >>= 1)
            v[q] += __shfl_down_sync(0xffffffffu, v[q], off);
    }
    if (lane == 0) {
        #pragma unroll
        for (int q = 0; q < 6; ++q) red[warp][q] = v[q];
    }
    __syncthreads();   // also fences all histogram writes
    if (tid < 6) {
        float s = 0.f;
        #pragma unroll
        for (int w = 0; w < 4; ++w) s += red[w][tid];
        atomicAdd(&g_acc[tid], s);
    }

    // ---- reduce packed histogram: warp w handles bins 8w..8w+7 ----
    #pragma unroll
    for (int bb = 0; bb < 8; ++bb) {
        int bin = (warp << 3) + bb;
        float cs = 0.f, ss = 0.f;
        #pragma unroll
        for (int k = 0; k < BTH / 32; ++k) {
            float vv = hist[bin * BTH + lane + k * 32];
            float cc = floorf(vv * 0.015625f);          // count
            cs += cc;
            ss += fmaf(cc, -64.f, vv);                  // sum of p
        }
        #pragma unroll
        for (int off = 16; off; off >>= 1) {
            cs += __shfl_down_sync(0xffffffffu, cs, off);
            ss += __shfl_down_sync(0xffffffffu, ss, off);
        }
        if (lane == 0) {
            atomicAdd(&g_seg_sum[b * NUM_IDS + bin], ss);
            atomicAdd(&g_seg_cnt[b * NUM_IDS + bin], cs);
        }
    }
}

// ===========================================================================
// finalize + self-reset
// ===========================================================================
__global__ void finalize_kernel(float* __restrict__ out, int out_size) {
    __shared__ float cim[NB];
    __shared__ float psum[NB];
    const int tid  = threadIdx.x;        // 512 threads
    const int warp = tid >> 5;           // image
    const int lane = tid & 31;           // id

    float s = g_seg_sum[tid];
    float c = g_seg_cnt[tid];
    float m = s / fmaxf(c, 1.f);
    bool valid = (c > 0.f) && (lane > 0);
    unsigned vm = __ballot_sync(0xffffffffu, valid);

    float csum = 0.f, np = 0.f;
    #pragma unroll
    for (int k = 0; k < 32; ++k) {
        float mk = __shfl_sync(0xffffffffu, m, k);
        if (valid && (k < lane) && ((vm >> k) & 1u)) {
            csum += expf(-fabsf(m - mk));
            np += 1.f;
        }
    }
    float ss = s;
    #pragma unroll
    for (int off = 16; off; off >>= 1) {
        csum += __shfl_down_sync(0xffffffffu, csum, off);
        np   += __shfl_down_sync(0xffffffffu, np,   off);
        ss   += __shfl_down_sync(0xffffffffu, ss,   off);
    }
    if (lane == 0) {
        cim[warp]  = (np > 0.f) ? csum / fmaxf(np, 1.f) : 0.f;
        psum[warp] = ss;
    }
    __syncthreads();

    if (tid == 0) {
        float contrast = 0.f, sum_p = 0.f;
        #pragma unroll
        for (int k = 0; k < NB; ++k) { contrast += cim[k]; sum_p += psum[k]; }
        contrast *= (1.f / (float)NB);

        const float N = (float)NB * (float)NH * (float)NW;
        float focal = g_acc[ACC_FOCAL] / N;
        float dice  = 1.f - (2.f * g_acc[ACC_SUMPT] + 1e-6f)
                          / (sum_p + g_acc[ACC_SUMT] + 1e-6f);
        float lm    = g_acc[ACC_MAG] / N;
        float msum  = g_acc[ACC_MCNT];
        float dl    = (msum > 0.f) ? g_acc[ACC_DIR] / fmaxf(msum, 1.f) : 0.f;
        float total = focal + dice + 0.5f * (lm + dl) + 0.1f * contrast;
        for (int i = 0; i < out_size; ++i) out[i] = total;
    }
    __syncthreads();   // all reads done before reset

    g_seg_sum[tid] = 0.f;
    g_seg_cnt[tid] = 0.f;
    if (tid < 8) g_acc[tid] = 0.f;
}

extern "C" void kernel_launch(void* const* d_in, const int* in_sizes, int n_in,
                              void* d_out, int out_size) {
    const float* pred = (const float*)d_in[0];
    const float* tgt  = (const float*)d_in[1];
    const int*   ids  = (const int*)d_in[2];
    float* out = (float*)d_out;

    dim3 grid(NW / 128, NH / (4 * R_ROWS), NB);   // (8, 32, 16) = 4096 blocks
    loss_main<<<grid, BTH>>>((const float4*)pred, (const float4*)tgt,
                             (const int4*)ids);

    finalize_kernel<<<1, 512>>>(out, out_size);
}

// round 8
// speedup vs baseline: 1.0502x; 1.0502x over previous
#include <cuda_runtime.h>

// ---------------------------------------------------------------------------
// EnhancedSegmentationLoss
//   loss_main : streaming Sobel + focal + dice (R5 structure, proven 52us)
//   seg_kernel: packed per-thread histograms (v += 64+p), prefetch pipeline,
//               last block performs finalize inline (no 3rd launch)
// ---------------------------------------------------------------------------

#define NB 16
#define NH 1024
#define NW 1024
#define NW4 (NW / 4)
#define NUM_IDS 32
#define R_ROWS 8

#define ACC_FOCAL 0
#define ACC_SUMT  1
#define ACC_SUMPT 2
#define ACC_MAG   3
#define ACC_DIR   4
#define ACC_MCNT  5

__device__ float g_acc[8];
__device__ float g_seg_sum[NB * NUM_IDS];
__device__ float g_seg_cnt[NB * NUM_IDS];
__device__ unsigned g_ctr;

__device__ __forceinline__ float sigf(float x) {
    return __fdividef(1.f, 1.f + __expf(-x));
}

// ===========================================================================
// Kernel 1: streaming stencil (unchanged from R5)
// ===========================================================================
__device__ __forceinline__ void row_terms(
    float4 pv, float4 tv, float pe, float te, int lane,
    float* __restrict__ dp, float* __restrict__ sp,
    float* __restrict__ dt, float* __restrict__ st,
    float* __restrict__ pout)
{
    float p0 = sigf(pv.x), p1 = sigf(pv.y), p2 = sigf(pv.z), p3 = sigf(pv.w);
    float pes = sigf(pe);

    float pl = __shfl_up_sync(0xffffffffu, p3, 1);    if (lane == 0)  pl = pes;
    float pr = __shfl_down_sync(0xffffffffu, p0, 1);  if (lane == 31) pr = pes;
    float tl = __shfl_up_sync(0xffffffffu, tv.w, 1);  if (lane == 0)  tl = te;
    float tr = __shfl_down_sync(0xffffffffu, tv.x, 1);if (lane == 31) tr = te;

    dp[0] = 0.125f * (p1 - pl);     dp[1] = 0.125f * (p2 - p0);
    dp[2] = 0.125f * (p3 - p1);     dp[3] = 0.125f * (pr - p2);
    sp[0] = fmaf(0.25f, p0, 0.125f * (pl + p1));
    sp[1] = fmaf(0.25f, p1, 0.125f * (p0 + p2));
    sp[2] = fmaf(0.25f, p2, 0.125f * (p1 + p3));
    sp[3] = fmaf(0.25f, p3, 0.125f * (p2 + pr));
    dt[0] = 0.125f * (tv.y - tl);   dt[1] = 0.125f * (tv.z - tv.x);
    dt[2] = 0.125f * (tv.w - tv.y); dt[3] = 0.125f * (tr - tv.z);
    st[0] = fmaf(0.25f, tv.x, 0.125f * (tl + tv.y));
    st[1] = fmaf(0.25f, tv.y, 0.125f * (tv.x + tv.z));
    st[2] = fmaf(0.25f, tv.z, 0.125f * (tv.y + tv.w));
    st[3] = fmaf(0.25f, tv.w, 0.125f * (tv.z + tr));

    pout[0] = p0; pout[1] = p1; pout[2] = p2; pout[3] = p3;
}

__device__ __forceinline__ void pointwise(
    const float* __restrict__ p, float4 tv,
    float& fl, float& sts, float& spt)
{
    float tt[4] = {tv.x, tv.y, tv.z, tv.w};
    #pragma unroll
    for (int i = 0; i < 4; ++i) {
        float ep  = 1.f - p[i];
        bool  one = (tt[i] == 1.f);
        float pt  = one ? p[i] : ep;
        float om  = one ? ep : p[i];
        float aw  = one ? 0.25f : 0.75f;
        fl  = fmaf(aw * om * om, -__logf(pt), fl);
        sts += tt[i];
        spt = fmaf(tt[i], p[i], spt);
    }
}

__device__ __forceinline__ void stencil_out(
    const float* dpA, const float* spA, const float* dtA, const float* stA,
    const float* dpB, const float* dtB,
    const float* dpC, const float* spC, const float* dtC, const float* stC,
    float& mag, float& dsum, float& mcnt)
{
    #pragma unroll
    for (int i = 0; i < 4; ++i) {
        float pgx = fmaf(2.f, dpB[i], dpA[i] + dpC[i]);
        float pgy = spC[i] - spA[i];
        float tgx = fmaf(2.f, dtB[i], dtA[i] + dtC[i]);
        float tgy = stC[i] - stA[i];
        float pq = fmaf(pgx, pgx, fmaf(pgy, pgy, 1e-6f));
        float tq = fmaf(tgx, tgx, fmaf(tgy, tgy, 1e-6f));
        float rp = rsqrtf(pq), rt = rsqrtf(tq);
        float pm = pq * rp,    tm = tq * rt;
        float bw = fmaf(5.f, tm, 1.f);
        float dm = (pm - tm) * bw;
        mag = fmaf(dm, dm, mag);
        float sel = (tm > 0.1f) ? 1.f : 0.f;
        float cosv = fmaf(tgx, pgx, tgy * pgy) * (rt * rp);
        dsum = fmaf(sel, 1.f - cosv, dsum);
        mcnt += sel;
    }
}

__global__ __launch_bounds__(128, 5) void loss_main(
    const float4* __restrict__ pred4,
    const float4* __restrict__ tgt4)
{
    __shared__ float red[4][6];
    const int lane = threadIdx.x & 31;
    const int warp = threadIdx.x >> 5;
    const int b  = blockIdx.z;
    const int x0 = blockIdx.x * 128;
    const int ys = blockIdx.y * (4 * R_ROWS) + warp * R_ROWS;

    const int  c4   = (x0 >> 2) + lane;
    const bool edge = (lane == 0) | (lane == 31);
    const int  xe   = (lane == 0) ? max(x0 - 1, 0) : min(x0 + 128, NW - 1);

    const float4* P4 = pred4 + (size_t)b * (NH * NW4) + (size_t)ys * NW4 + c4;
    const float4* T4 = tgt4  + (size_t)b * (NH * NW4) + (size_t)ys * NW4 + c4;
    const float*  Ps = (const float*)pred4 + (size_t)b * NH * NW + (size_t)ys * NW + xe;
    const float*  Ts = (const float*)tgt4  + (size_t)b * NH * NW + (size_t)ys * NW + xe;

    const int top4 = (ys == 0) ? 0 : -NW4;
    const int topS = (ys == 0) ? 0 : -NW;
    const int bot4 = (ys + R_ROWS >= NH) ? (R_ROWS - 1) * NW4 : R_ROWS * NW4;
    const int botS = (ys + R_ROWS >= NH) ? (R_ROWS - 1) * NW  : R_ROWS * NW;

    float fl = 0.f, sts = 0.f, spt = 0.f;
    float mag = 0.f, dsum = 0.f, mcnt = 0.f;

    float dpA[4], spA[4], dtA[4], stA[4];
    float dpB[4], spB[4], dtB[4], stB[4];
    float dpC[4], spC[4], dtC[4], stC[4];
    float pc[4];

    {
        float4 pv = P4[top4], tv = T4[top4];
        float pe = 0.f, te = 0.f;
        if (edge) { pe = Ps[topS]; te = Ts[topS]; }
        row_terms(pv, tv, pe, te, lane, dpA, spA, dtA, stA, pc);
    }
    {
        float4 pv = P4[0], tv = T4[0];
        float pe = 0.f, te = 0.f;
        if (edge) { pe = Ps[0]; te = Ts[0]; }
        row_terms(pv, tv, pe, te, lane, dpB, spB, dtB, stB, pc);
        pointwise(pc, tv, fl, sts, spt);
    }

    #pragma unroll
    for (int j = 0; j < R_ROWS; ++j) {
        const int o4 = (j == R_ROWS - 1) ? bot4 : (j + 1) * NW4;
        const int oS = (j == R_ROWS - 1) ? botS : (j + 1) * NW;
        float4 pv = P4[o4], tv = T4[o4];
        float pe = 0.f, te = 0.f;
        if (edge) { pe = Ps[oS]; te = Ts[oS]; }
        row_terms(pv, tv, pe, te, lane, dpC, spC, dtC, stC, pc);
        if (j < R_ROWS - 1) pointwise(pc, tv, fl, sts, spt);

        stencil_out(dpA, spA, dtA, stA, dpB, dtB, dpC, spC, dtC, stC,
                    mag, dsum, mcnt);

        #pragma unroll
        for (int i = 0; i < 4; ++i) {
            dpA[i] = dpB[i]; spA[i] = spB[i]; dtA[i] = dtB[i]; stA[i] = stB[i];
            dpB[i] = dpC[i]; spB[i] = spC[i]; dtB[i] = dtC[i]; stB[i] = stC[i];
        }
    }

    float v[6] = {fl, sts, spt, mag, dsum, mcnt};
    #pragma unroll
    for (int q = 0; q < 6; ++q) {
        #pragma unroll
        for (int off = 16; off; off >>= 1)
            v[q] += __shfl_down_sync(0xffffffffu, v[q], off);
    }
    if (lane == 0) {
        #pragma unroll
        for (int q = 0; q < 6; ++q) red[warp][q] = v[q];
    }
    __syncthreads();
    if (threadIdx.x < 6) {
        float s = 0.f;
        #pragma unroll
        for (int w = 0; w < 4; ++w) s += red[w][threadIdx.x];
        atomicAdd(&g_acc[threadIdx.x], s);
    }
}

// ===========================================================================
// Kernel 2: segment sums via packed histograms (v = sum of (64 + p)), with
// inline finalize in the last-arriving block.
// ===========================================================================
#define SEG_BTH 256
#define SEG_BLOCKS_PER_IMG 128
#define SEG_PX_PER_BLOCK   (NH * NW / SEG_BLOCKS_PER_IMG)   // 8192 -> 32 px/thr
#define SEG_ITERS          (SEG_PX_PER_BLOCK / (SEG_BTH * 4)) // 8
#define SEG_NBLK           (SEG_BLOCKS_PER_IMG * NB)          // 2048

__global__ __launch_bounds__(SEG_BTH) void seg_kernel(
    const float4* __restrict__ pred4,
    const int4*   __restrict__ ids4,
    float* __restrict__ out, int out_size)
{
    __shared__ float hist[NUM_IDS * SEG_BTH];   // 32 KB packed count|sum

    const int tid = threadIdx.x;
    {
        float4 z = make_float4(0.f, 0.f, 0.f, 0.f);
        float4* h4 = (float4*)hist;
        #pragma unroll
        for (int i = 0; i < (NUM_IDS * SEG_BTH / 4) / SEG_BTH; ++i)
            h4[tid + i * SEG_BTH] = z;
    }
    __syncthreads();

    const int b = blockIdx.y;
    const size_t base4 = (((size_t)b * NH * NW) + (size_t)blockIdx.x * SEG_PX_PER_BLOCK) >> 2;

    // software-pipelined: next loads in flight while updating current
    float4 x  = pred4[base4 + tid];
    int4   id = ids4 [base4 + tid];
    #pragma unroll
    for (int k = 0; k < SEG_ITERS; ++k) {
        float4 xn; int4 idn;
        if (k < SEG_ITERS - 1) {
            size_t g = base4 + (size_t)(k + 1) * SEG_BTH + tid;
            xn = pred4[g]; idn = ids4[g];
        }
        float p0 = sigf(x.x), p1 = sigf(x.y), p2 = sigf(x.z), p3 = sigf(x.w);
        hist[(id.x & 31) * SEG_BTH + tid] += (64.f + p0);
        hist[(id.y & 31) * SEG_BTH + tid] += (64.f + p1);
        hist[(id.z & 31) * SEG_BTH + tid] += (64.f + p2);
        hist[(id.w & 31) * SEG_BTH + tid] += (64.f + p3);
        x = xn; id = idn;
    }
    __syncthreads();

    // reduce: warp w handles bins 4w..4w+3 (8 warps x 4 bins)
    const int lane = tid & 31, warp = tid >> 5;
    #pragma unroll
    for (int bb = 0; bb < 4; ++bb) {
        int bin = (warp << 2) + bb;
        float cs = 0.f, ss = 0.f;
        #pragma unroll
        for (int k = 0; k < SEG_BTH / 32; ++k) {
            float vv = hist[bin * SEG_BTH + lane + k * 32];
            float cc = floorf(vv * 0.015625f);
            cs += cc;
            ss += fmaf(cc, -64.f, vv);
        }
        #pragma unroll
        for (int off = 16; off; off >>= 1) {
            cs += __shfl_down_sync(0xffffffffu, cs, off);
            ss += __shfl_down_sync(0xffffffffu, ss, off);
        }
        if (lane == 0) {
            atomicAdd(&g_seg_sum[b * NUM_IDS + bin], ss);
            atomicAdd(&g_seg_cnt[b * NUM_IDS + bin], cs);
        }
    }

    // ---- last-block finalize ----
    __shared__ bool is_last;
    __threadfence();
    if (tid == 0) is_last = (atomicAdd(&g_ctr, 1u) == SEG_NBLK - 1);
    __syncthreads();
    if (!is_last) return;

    __shared__ float cim[NB];
    __shared__ float psum[NB];
    // 8 warps, each handles 2 images
    for (int img = warp; img < NB; img += 8) {
        float s = g_seg_sum[img * NUM_IDS + lane];
        float c = g_seg_cnt[img * NUM_IDS + lane];
        float m = s / fmaxf(c, 1.f);
        bool valid = (c > 0.f) && (lane > 0);
        unsigned vm = __ballot_sync(0xffffffffu, valid);

        float csum = 0.f, np = 0.f;
        #pragma unroll
        for (int k = 0; k < 32; ++k) {
            float mk = __shfl_sync(0xffffffffu, m, k);
            if (valid && (k < lane) && ((vm >> k) & 1u)) {
                csum += expf(-fabsf(m - mk));
                np += 1.f;
            }
        }
        float ss = s;
        #pragma unroll
        for (int off = 16; off; off >>= 1) {
            csum += __shfl_down_sync(0xffffffffu, csum, off);
            np   += __shfl_down_sync(0xffffffffu, np,   off);
            ss   += __shfl_down_sync(0xffffffffu, ss,   off);
        }
        if (lane == 0) {
            cim[img]  = (np > 0.f) ? csum / fmaxf(np, 1.f) : 0.f;
            psum[img] = ss;
        }
    }
    __syncthreads();

    if (tid == 0) {
        float contrast = 0.f, sum_p = 0.f;
        #pragma unroll
        for (int k = 0; k < NB; ++k) { contrast += cim[k]; sum_p += psum[k]; }
        contrast *= (1.f / (float)NB);

        const float N = (float)NB * (float)NH * (float)NW;
        float focal = g_acc[ACC_FOCAL] / N;
        float dice  = 1.f - (2.f * g_acc[ACC_SUMPT] + 1e-6f)
                          / (sum_p + g_acc[ACC_SUMT] + 1e-6f);
        float lm    = g_acc[ACC_MAG] / N;
        float msum  = g_acc[ACC_MCNT];
        float dl    = (msum > 0.f) ? g_acc[ACC_DIR] / fmaxf(msum, 1.f) : 0.f;
        float total = focal + dice + 0.5f * (lm + dl) + 0.1f * contrast;
        for (int i = 0; i < out_size; ++i) out[i] = total;
    }
    __syncthreads();   // all reads done before reset

    // self-reset for next graph replay
    for (int i = tid; i < NB * NUM_IDS; i += SEG_BTH) {
        g_seg_sum[i] = 0.f;
        g_seg_cnt[i] = 0.f;
    }
    if (tid < 8) g_acc[tid] = 0.f;
    if (tid == 0) g_ctr = 0u;
}

extern "C" void kernel_launch(void* const* d_in, const int* in_sizes, int n_in,
                              void* d_out, int out_size) {
    const float* pred = (const float*)d_in[0];
    const float* tgt  = (const float*)d_in[1];
    const int*   ids  = (const int*)d_in[2];
    float* out = (float*)d_out;

    dim3 grid(NW / 128, NH / (4 * R_ROWS), NB);   // 4096 blocks
    loss_main<<<grid, 128>>>((const float4*)pred, (const float4*)tgt);

    dim3 sgrid(SEG_BLOCKS_PER_IMG, NB);           // 2048 blocks
    seg_kernel<<<sgrid, SEG_BTH>>>((const float4*)pred, (const int4*)ids,
                                   out, out_size);
}